// round 1
// baseline (speedup 1.0000x reference)
#include <cuda_runtime.h>
#include <cuda_bf16.h>
#include <cstdint>

// Problem constants (shapes fixed by the reference)
#define MAXN    100000
#define INF     128
#define HID     64

// Scratch feature tables: 100000 x 64 f32 each (25.6 MB). Device globals per the
// allocation rules.
__device__ float g_buf0[(size_t)MAXN * HID];
__device__ float g_buf1[(size_t)MAXN * HID];

// ---------------------------------------------------------------------------
// zero: grid-stride float4 clear
// ---------------------------------------------------------------------------
__global__ void zero_kernel(float* __restrict__ p, int n_f4) {
    int i = blockIdx.x * blockDim.x + threadIdx.x;
    float4 z = make_float4(0.f, 0.f, 0.f, 0.f);
    for (; i < n_f4; i += gridDim.x * blockDim.x)
        reinterpret_cast<float4*>(p)[i] = z;
}

// ---------------------------------------------------------------------------
// GEMM1: Y[n,64] = X[n,128] @ W[128,64]
// 64-row tile per block, 256 threads, 4x4 micro-tile, K=128.
// Dynamic smem: xs[128][64] (x transposed, k-major) + ws[128][64]  = 64 KB
// ---------------------------------------------------------------------------
__global__ __launch_bounds__(256) void gemm_in_kernel(
    const float* __restrict__ X, const float* __restrict__ W,
    float* __restrict__ Y, int n)
{
    extern __shared__ float sm[];
    float* xs = sm;               // [128][64] : xs[k*64 + r]
    float* ws = sm + 128 * 64;    // [128][64] : ws[k*64 + c]

    const int tid = threadIdx.x;
    const int row0 = blockIdx.x * 64;

    // Load W (8192 floats = 2048 float4), layout matches [128][64] row-major.
    #pragma unroll
    for (int q = tid; q < 2048; q += 256)
        reinterpret_cast<float4*>(ws)[q] = reinterpret_cast<const float4*>(W)[q];

    // Load X tile transposed: 2048 float4; q -> (row = q%64, k4 = q/64)
    #pragma unroll
    for (int it = 0; it < 8; it++) {
        int q   = tid + it * 256;
        int row = q & 63;
        int k4  = q >> 6;                 // 0..31
        int gr  = row0 + row;
        float4 v = make_float4(0.f, 0.f, 0.f, 0.f);
        if (gr < n)
            v = reinterpret_cast<const float4*>(X + (size_t)gr * INF)[k4];
        xs[(4 * k4 + 0) * 64 + row] = v.x;
        xs[(4 * k4 + 1) * 64 + row] = v.y;
        xs[(4 * k4 + 2) * 64 + row] = v.z;
        xs[(4 * k4 + 3) * 64 + row] = v.w;
    }
    __syncthreads();

    const int tr = tid & 15;   // row group: rows 4*tr .. 4*tr+3
    const int tc = tid >> 4;   // col group: cols 4*tc .. 4*tc+3

    float c[4][4];
    #pragma unroll
    for (int i = 0; i < 4; i++)
        #pragma unroll
        for (int j = 0; j < 4; j++) c[i][j] = 0.f;

    #pragma unroll 8
    for (int k = 0; k < 128; k++) {
        float4 a = *reinterpret_cast<const float4*>(xs + k * 64 + 4 * tr);
        float4 b = *reinterpret_cast<const float4*>(ws + k * 64 + 4 * tc);
        float av[4] = {a.x, a.y, a.z, a.w};
        float bv[4] = {b.x, b.y, b.z, b.w};
        #pragma unroll
        for (int i = 0; i < 4; i++)
            #pragma unroll
            for (int j = 0; j < 4; j++)
                c[i][j] = fmaf(av[i], bv[j], c[i][j]);
    }

    #pragma unroll
    for (int i = 0; i < 4; i++) {
        int gr = row0 + 4 * tr + i;
        if (gr < n) {
            float4 v = make_float4(c[i][0], c[i][1], c[i][2], c[i][3]);
            reinterpret_cast<float4*>(Y + (size_t)gr * HID)[tc] = v;
        }
    }
}

// ---------------------------------------------------------------------------
// SpMM scatter: for each edge e: dst[row[e]] += val[e] * src[col[e]]
// 16 threads per edge, each handles a float4 lane; vector RED to L2.
// ---------------------------------------------------------------------------
__global__ __launch_bounds__(256) void spmm_kernel(
    const int*   __restrict__ erow, const int* __restrict__ ecol,
    const float* __restrict__ eval,
    const float* __restrict__ src, float* __restrict__ dst, int E)
{
    int gid = blockIdx.x * blockDim.x + threadIdx.x;
    int e = gid >> 4;
    if (e >= E) return;
    int j = gid & 15;

    int   r = __ldg(erow + e);
    int   c = __ldg(ecol + e);
    float v = __ldg(eval + e);

    float4 s = __ldg(reinterpret_cast<const float4*>(src + (size_t)c * HID) + j);
    float4 m = make_float4(s.x * v, s.y * v, s.z * v, s.w * v);
    float* d = dst + (size_t)r * HID + 4 * j;
    asm volatile("red.global.add.v4.f32 [%0], {%1,%2,%3,%4};"
                 :: "l"(d), "f"(m.x), "f"(m.y), "f"(m.z), "f"(m.w) : "memory");
}

// ---------------------------------------------------------------------------
// GEMM2 fused: Y[n,64] = relu(Hacc[n,64] + b1) @ W2[64,64]
// 64-row tile, 256 threads, 4x4 micro-tile, K=64. Static smem 32 KB + bias.
// ---------------------------------------------------------------------------
__global__ __launch_bounds__(256) void gemm_hid_kernel(
    const float* __restrict__ Hacc, const float* __restrict__ bias,
    const float* __restrict__ W2, float* __restrict__ Y, int n)
{
    __shared__ float hs[64 * 64];   // hs[k*64 + r] (transposed, post bias+relu)
    __shared__ float ws[64 * 64];   // ws[k*64 + c]
    __shared__ float bs[64];

    const int tid = threadIdx.x;
    const int row0 = blockIdx.x * 64;

    if (tid < 64) bs[tid] = bias[tid];
    // W2: 4096 floats = 1024 float4
    #pragma unroll
    for (int q = tid; q < 1024; q += 256)
        reinterpret_cast<float4*>(ws)[q] = reinterpret_cast<const float4*>(W2)[q];
    __syncthreads();  // bs ready before use below

    // H tile: 1024 float4; q -> (row = q%64, k4 = q/64), apply bias + relu
    #pragma unroll
    for (int it = 0; it < 4; it++) {
        int q   = tid + it * 256;
        int row = q & 63;
        int k4  = q >> 6;       // 0..15
        int gr  = row0 + row;
        float4 v = make_float4(0.f, 0.f, 0.f, 0.f);
        if (gr < n)
            v = reinterpret_cast<const float4*>(Hacc + (size_t)gr * HID)[k4];
        hs[(4 * k4 + 0) * 64 + row] = fmaxf(v.x + bs[4 * k4 + 0], 0.f);
        hs[(4 * k4 + 1) * 64 + row] = fmaxf(v.y + bs[4 * k4 + 1], 0.f);
        hs[(4 * k4 + 2) * 64 + row] = fmaxf(v.z + bs[4 * k4 + 2], 0.f);
        hs[(4 * k4 + 3) * 64 + row] = fmaxf(v.w + bs[4 * k4 + 3], 0.f);
    }
    __syncthreads();

    const int tr = tid & 15;
    const int tc = tid >> 4;

    float c[4][4];
    #pragma unroll
    for (int i = 0; i < 4; i++)
        #pragma unroll
        for (int j = 0; j < 4; j++) c[i][j] = 0.f;

    #pragma unroll 8
    for (int k = 0; k < 64; k++) {
        float4 a = *reinterpret_cast<const float4*>(hs + k * 64 + 4 * tr);
        float4 b = *reinterpret_cast<const float4*>(ws + k * 64 + 4 * tc);
        float av[4] = {a.x, a.y, a.z, a.w};
        float bv[4] = {b.x, b.y, b.z, b.w};
        #pragma unroll
        for (int i = 0; i < 4; i++)
            #pragma unroll
            for (int j = 0; j < 4; j++)
                c[i][j] = fmaf(av[i], bv[j], c[i][j]);
    }

    #pragma unroll
    for (int i = 0; i < 4; i++) {
        int gr = row0 + 4 * tr + i;
        if (gr < n) {
            float4 v = make_float4(c[i][0], c[i][1], c[i][2], c[i][3]);
            reinterpret_cast<float4*>(Y + (size_t)gr * HID)[tc] = v;
        }
    }
}

// ---------------------------------------------------------------------------
// Head: out[n] = relu(Hacc[n] + b2) . lin_W + lin_b      (one warp per row)
// ---------------------------------------------------------------------------
__global__ __launch_bounds__(256) void head_kernel(
    const float* __restrict__ Hacc, const float* __restrict__ b2,
    const float* __restrict__ linW, const float* __restrict__ linb,
    float* __restrict__ out, int n)
{
    int warp = (blockIdx.x * blockDim.x + threadIdx.x) >> 5;
    int lane = threadIdx.x & 31;
    if (warp >= n) return;

    float2 hv = *reinterpret_cast<const float2*>(Hacc + (size_t)warp * HID + 2 * lane);
    float2 bv = *reinterpret_cast<const float2*>(b2 + 2 * lane);
    float2 wv = *reinterpret_cast<const float2*>(linW + 2 * lane);
    float a0 = fmaxf(hv.x + bv.x, 0.f);
    float a1 = fmaxf(hv.y + bv.y, 0.f);
    float s = a0 * wv.x + a1 * wv.y;
    #pragma unroll
    for (int o = 16; o > 0; o >>= 1)
        s += __shfl_xor_sync(0xFFFFFFFFu, s, o);
    if (lane == 0) out[warp] = s + linb[0];
}

// ---------------------------------------------------------------------------
// kernel_launch
// Inputs (metadata order): x, edge_row, edge_col, edge_val, W1, b1, W2, b2,
//                          lin_W, lin_b
// ---------------------------------------------------------------------------
extern "C" void kernel_launch(void* const* d_in, const int* in_sizes, int n_in,
                              void* d_out, int out_size)
{
    const float* x    = (const float*)d_in[0];
    const int*   erow = (const int*)  d_in[1];
    const int*   ecol = (const int*)  d_in[2];
    const float* eval = (const float*)d_in[3];
    const float* W1   = (const float*)d_in[4];
    const float* b1   = (const float*)d_in[5];
    const float* W2   = (const float*)d_in[6];
    const float* b2   = (const float*)d_in[7];
    const float* linW = (const float*)d_in[8];
    const float* linb = (const float*)d_in[9];
    float* out = (float*)d_out;

    const int n = in_sizes[0] / INF;
    const int E = in_sizes[1];

    float *buf0, *buf1;
    cudaGetSymbolAddress((void**)&buf0, g_buf0);
    cudaGetSymbolAddress((void**)&buf1, g_buf1);

    // 64 KB dynamic smem for gemm_in (idempotent attribute set)
    static bool attr_done = false;
    if (!attr_done) {
        cudaFuncSetAttribute(gemm_in_kernel,
                             cudaFuncAttributeMaxDynamicSharedMemorySize, 65536);
        attr_done = true;
    }

    const int nf4        = n * HID / 4;
    const int zero_grid  = 2048;
    const int gemm_grid  = (n + 63) / 64;
    const long long spmm_threads = (long long)E * 16;
    const int spmm_grid  = (int)((spmm_threads + 255) / 256);
    const int head_grid  = (n * 32 + 255) / 256;

    // Layer 1: buf0 = x@W1 ; buf1 = A@buf0
    gemm_in_kernel<<<gemm_grid, 256, 65536>>>(x, W1, buf0, n);
    zero_kernel<<<zero_grid, 256>>>(buf1, nf4);
    spmm_kernel<<<spmm_grid, 256>>>(erow, ecol, eval, buf0, buf1, E);

    // Layer 2: buf0 = relu(buf1+b1)@W2 ; buf1 = A@buf0
    gemm_hid_kernel<<<gemm_grid, 256>>>(buf1, b1, W2, buf0, n);
    zero_kernel<<<zero_grid, 256>>>(buf1, nf4);
    spmm_kernel<<<spmm_grid, 256>>>(erow, ecol, eval, buf0, buf1, E);

    // Head
    head_kernel<<<head_grid, 256>>>(buf1, b2, linW, linb, out, n);
}

// round 2
// speedup vs baseline: 1.5362x; 1.5362x over previous
#include <cuda_runtime.h>
#include <cuda_bf16.h>
#include <cstdint>

// Problem constants (shapes fixed by the reference)
#define MAXN    100000
#define MAXE    3400000
#define INF     128
#define HID     64

// Scratch (device globals per allocation rules)
__device__ float g_buf0[(size_t)MAXN * HID];   // feature table A (25.6 MB)
__device__ float g_buf1[(size_t)MAXN * HID];   // feature table B (25.6 MB)
__device__ int   g_deg[MAXN];
__device__ int   g_rptr[MAXN + 1];
__device__ int   g_wcur[MAXN];
__device__ int2  g_cv[MAXE];                   // (col, val-bits) sorted by row
__device__ int   g_partial[256];

// ---------------------------------------------------------------------------
// CSR build: zero-deg, histogram, 3-pass scan, counting-sort scatter
// ---------------------------------------------------------------------------
__global__ void zero_deg_kernel(int* __restrict__ deg, int n) {
    int i = blockIdx.x * blockDim.x + threadIdx.x;
    for (; i < n; i += gridDim.x * blockDim.x) deg[i] = 0;
}

__global__ void hist_kernel(const int* __restrict__ erow, int* __restrict__ deg, int E) {
    int i = blockIdx.x * blockDim.x + threadIdx.x;
    for (; i < E; i += gridDim.x * blockDim.x)
        atomicAdd(deg + __ldg(erow + i), 1);
}

// block b sums deg[b*1024 .. b*1024+1023] -> partial[b]   (256 thr, 4 elems each)
__global__ __launch_bounds__(256) void partial_kernel(
    const int* __restrict__ deg, int* __restrict__ partial, int n)
{
    __shared__ int sh[256];
    int tid = threadIdx.x;
    int base = blockIdx.x * 1024 + tid * 4;
    int s = 0;
    #pragma unroll
    for (int j = 0; j < 4; j++) if (base + j < n) s += deg[base + j];
    sh[tid] = s; __syncthreads();
    for (int off = 128; off > 0; off >>= 1) {
        if (tid < off) sh[tid] += sh[tid + off];
        __syncthreads();
    }
    if (tid == 0) partial[blockIdx.x] = sh[0];
}

// exclusive scan of partials (nb <= 128), writes rptr[n] = total
__global__ __launch_bounds__(128) void scanp_kernel(
    int* __restrict__ partial, int* __restrict__ rptr, int nb, int n)
{
    __shared__ int sh[128];
    int tid = threadIdx.x;
    int v = (tid < nb) ? partial[tid] : 0;
    sh[tid] = v; __syncthreads();
    #pragma unroll
    for (int off = 1; off < 128; off <<= 1) {
        int y = (tid >= off) ? sh[tid - off] : 0;
        __syncthreads();
        sh[tid] += y;
        __syncthreads();
    }
    if (tid < nb) partial[tid] = sh[tid] - v;          // exclusive
    if (tid == 127) rptr[n] = sh[127];                 // total
}

// final scan: rptr[i] and wcur[i] = global exclusive prefix of deg
__global__ __launch_bounds__(256) void scan_chunk_kernel(
    const int* __restrict__ deg, const int* __restrict__ partial,
    int* __restrict__ rptr, int* __restrict__ wcur, int n)
{
    __shared__ int sh[256];
    int tid = threadIdx.x;
    int base = blockIdx.x * 1024 + tid * 4;
    int v[4]; int s = 0;
    #pragma unroll
    for (int j = 0; j < 4; j++) {
        v[j] = (base + j < n) ? deg[base + j] : 0;
        s += v[j];
    }
    sh[tid] = s; __syncthreads();
    #pragma unroll
    for (int off = 1; off < 256; off <<= 1) {
        int y = (tid >= off) ? sh[tid - off] : 0;
        __syncthreads();
        sh[tid] += y;
        __syncthreads();
    }
    int excl = sh[tid] - s + partial[blockIdx.x];
    #pragma unroll
    for (int j = 0; j < 4; j++) {
        if (base + j < n) { rptr[base + j] = excl; wcur[base + j] = excl; }
        excl += v[j];
    }
}

__global__ void scatter_kernel(
    const int* __restrict__ erow, const int* __restrict__ ecol,
    const float* __restrict__ eval,
    int* __restrict__ wcur, int2* __restrict__ cv, int E)
{
    int i = blockIdx.x * blockDim.x + threadIdx.x;
    for (; i < E; i += gridDim.x * blockDim.x) {
        int r = __ldg(erow + i);
        int p = atomicAdd(wcur + r, 1);
        cv[p] = make_int2(__ldg(ecol + i), __float_as_int(__ldg(eval + i)));
    }
}

// ---------------------------------------------------------------------------
// GEMM1: Y[n,64] = X[n,128] @ W[128,64]
// 64-row tile per block, 256 threads, 4x4 micro-tile. Dyn smem 64 KB.
// ---------------------------------------------------------------------------
__global__ __launch_bounds__(256) void gemm_in_kernel(
    const float* __restrict__ X, const float* __restrict__ W,
    float* __restrict__ Y, int n)
{
    extern __shared__ float sm[];
    float* xs = sm;               // [128][64] : xs[k*64 + r]
    float* ws = sm + 128 * 64;    // [128][64] : ws[k*64 + c]

    const int tid = threadIdx.x;
    const int row0 = blockIdx.x * 64;

    #pragma unroll
    for (int q = tid; q < 2048; q += 256)
        reinterpret_cast<float4*>(ws)[q] = reinterpret_cast<const float4*>(W)[q];

    #pragma unroll
    for (int it = 0; it < 8; it++) {
        int q   = tid + it * 256;
        int row = q & 63;
        int k4  = q >> 6;
        int gr  = row0 + row;
        float4 v = make_float4(0.f, 0.f, 0.f, 0.f);
        if (gr < n)
            v = reinterpret_cast<const float4*>(X + (size_t)gr * INF)[k4];
        xs[(4 * k4 + 0) * 64 + row] = v.x;
        xs[(4 * k4 + 1) * 64 + row] = v.y;
        xs[(4 * k4 + 2) * 64 + row] = v.z;
        xs[(4 * k4 + 3) * 64 + row] = v.w;
    }
    __syncthreads();

    const int tr = tid & 15;
    const int tc = tid >> 4;

    float c[4][4];
    #pragma unroll
    for (int i = 0; i < 4; i++)
        #pragma unroll
        for (int j = 0; j < 4; j++) c[i][j] = 0.f;

    #pragma unroll 8
    for (int k = 0; k < 128; k++) {
        float4 a = *reinterpret_cast<const float4*>(xs + k * 64 + 4 * tr);
        float4 b = *reinterpret_cast<const float4*>(ws + k * 64 + 4 * tc);
        float av[4] = {a.x, a.y, a.z, a.w};
        float bv[4] = {b.x, b.y, b.z, b.w};
        #pragma unroll
        for (int i = 0; i < 4; i++)
            #pragma unroll
            for (int j = 0; j < 4; j++)
                c[i][j] = fmaf(av[i], bv[j], c[i][j]);
    }

    #pragma unroll
    for (int i = 0; i < 4; i++) {
        int gr = row0 + 4 * tr + i;
        if (gr < n) {
            float4 v = make_float4(c[i][0], c[i][1], c[i][2], c[i][3]);
            reinterpret_cast<float4*>(Y + (size_t)gr * HID)[tc] = v;
        }
    }
}

// ---------------------------------------------------------------------------
// CSR SpMM: warp per destination row, register accumulate, single store.
// ---------------------------------------------------------------------------
__global__ __launch_bounds__(256) void spmm_csr_kernel(
    const int* __restrict__ rptr, const int2* __restrict__ cv,
    const float* __restrict__ src, float* __restrict__ dst, int n)
{
    int row  = (blockIdx.x * blockDim.x + threadIdx.x) >> 5;
    int lane = threadIdx.x & 31;
    if (row >= n) return;

    int s = __ldg(rptr + row);
    int e = __ldg(rptr + row + 1);
    float ax = 0.f, ay = 0.f;

    int i = s;
    for (; i + 4 <= e; i += 4) {
        int2 c0 = __ldg(cv + i), c1 = __ldg(cv + i + 1);
        int2 c2 = __ldg(cv + i + 2), c3 = __ldg(cv + i + 3);
        float2 s0 = __ldg(reinterpret_cast<const float2*>(src + (size_t)c0.x * HID) + lane);
        float2 s1 = __ldg(reinterpret_cast<const float2*>(src + (size_t)c1.x * HID) + lane);
        float2 s2 = __ldg(reinterpret_cast<const float2*>(src + (size_t)c2.x * HID) + lane);
        float2 s3 = __ldg(reinterpret_cast<const float2*>(src + (size_t)c3.x * HID) + lane);
        float v0 = __int_as_float(c0.y), v1 = __int_as_float(c1.y);
        float v2 = __int_as_float(c2.y), v3 = __int_as_float(c3.y);
        ax = fmaf(v0, s0.x, ax); ay = fmaf(v0, s0.y, ay);
        ax = fmaf(v1, s1.x, ax); ay = fmaf(v1, s1.y, ay);
        ax = fmaf(v2, s2.x, ax); ay = fmaf(v2, s2.y, ay);
        ax = fmaf(v3, s3.x, ax); ay = fmaf(v3, s3.y, ay);
    }
    for (; i < e; i++) {
        int2 c0 = __ldg(cv + i);
        float2 s0 = __ldg(reinterpret_cast<const float2*>(src + (size_t)c0.x * HID) + lane);
        float v0 = __int_as_float(c0.y);
        ax = fmaf(v0, s0.x, ax); ay = fmaf(v0, s0.y, ay);
    }

    reinterpret_cast<float2*>(dst + (size_t)row * HID)[lane] = make_float2(ax, ay);
}

// Layer-2 SpMM fused with bias2 + ReLU + lin_W head: writes out[row] directly.
__global__ __launch_bounds__(256) void spmm_csr_head_kernel(
    const int* __restrict__ rptr, const int2* __restrict__ cv,
    const float* __restrict__ src,
    const float* __restrict__ b2, const float* __restrict__ linW,
    const float* __restrict__ linb, float* __restrict__ out, int n)
{
    int row  = (blockIdx.x * blockDim.x + threadIdx.x) >> 5;
    int lane = threadIdx.x & 31;
    if (row >= n) return;

    int s = __ldg(rptr + row);
    int e = __ldg(rptr + row + 1);
    float ax = 0.f, ay = 0.f;

    int i = s;
    for (; i + 4 <= e; i += 4) {
        int2 c0 = __ldg(cv + i), c1 = __ldg(cv + i + 1);
        int2 c2 = __ldg(cv + i + 2), c3 = __ldg(cv + i + 3);
        float2 s0 = __ldg(reinterpret_cast<const float2*>(src + (size_t)c0.x * HID) + lane);
        float2 s1 = __ldg(reinterpret_cast<const float2*>(src + (size_t)c1.x * HID) + lane);
        float2 s2 = __ldg(reinterpret_cast<const float2*>(src + (size_t)c2.x * HID) + lane);
        float2 s3 = __ldg(reinterpret_cast<const float2*>(src + (size_t)c3.x * HID) + lane);
        float v0 = __int_as_float(c0.y), v1 = __int_as_float(c1.y);
        float v2 = __int_as_float(c2.y), v3 = __int_as_float(c3.y);
        ax = fmaf(v0, s0.x, ax); ay = fmaf(v0, s0.y, ay);
        ax = fmaf(v1, s1.x, ax); ay = fmaf(v1, s1.y, ay);
        ax = fmaf(v2, s2.x, ax); ay = fmaf(v2, s2.y, ay);
        ax = fmaf(v3, s3.x, ax); ay = fmaf(v3, s3.y, ay);
    }
    for (; i < e; i++) {
        int2 c0 = __ldg(cv + i);
        float2 s0 = __ldg(reinterpret_cast<const float2*>(src + (size_t)c0.x * HID) + lane);
        float v0 = __int_as_float(c0.y);
        ax = fmaf(v0, s0.x, ax); ay = fmaf(v0, s0.y, ay);
    }

    // epilogue: relu(acc + b2) . linW, warp-reduce, + linb
    float2 bb = __ldg(reinterpret_cast<const float2*>(b2) + lane);
    float2 ww = __ldg(reinterpret_cast<const float2*>(linW) + lane);
    float a0 = fmaxf(ax + bb.x, 0.f);
    float a1 = fmaxf(ay + bb.y, 0.f);
    float sum = a0 * ww.x + a1 * ww.y;
    #pragma unroll
    for (int o = 16; o > 0; o >>= 1)
        sum += __shfl_xor_sync(0xFFFFFFFFu, sum, o);
    if (lane == 0) out[row] = sum + __ldg(linb);
}

// ---------------------------------------------------------------------------
// GEMM2 fused: Y[n,64] = relu(Hacc[n,64] + b1) @ W2[64,64]
// ---------------------------------------------------------------------------
__global__ __launch_bounds__(256) void gemm_hid_kernel(
    const float* __restrict__ Hacc, const float* __restrict__ bias,
    const float* __restrict__ W2, float* __restrict__ Y, int n)
{
    __shared__ float hs[64 * 64];
    __shared__ float ws[64 * 64];
    __shared__ float bs[64];

    const int tid = threadIdx.x;
    const int row0 = blockIdx.x * 64;

    if (tid < 64) bs[tid] = bias[tid];
    #pragma unroll
    for (int q = tid; q < 1024; q += 256)
        reinterpret_cast<float4*>(ws)[q] = reinterpret_cast<const float4*>(W2)[q];
    __syncthreads();

    #pragma unroll
    for (int it = 0; it < 4; it++) {
        int q   = tid + it * 256;
        int row = q & 63;
        int k4  = q >> 6;
        int gr  = row0 + row;
        float4 v = make_float4(0.f, 0.f, 0.f, 0.f);
        if (gr < n)
            v = reinterpret_cast<const float4*>(Hacc + (size_t)gr * HID)[k4];
        hs[(4 * k4 + 0) * 64 + row] = fmaxf(v.x + bs[4 * k4 + 0], 0.f);
        hs[(4 * k4 + 1) * 64 + row] = fmaxf(v.y + bs[4 * k4 + 1], 0.f);
        hs[(4 * k4 + 2) * 64 + row] = fmaxf(v.z + bs[4 * k4 + 2], 0.f);
        hs[(4 * k4 + 3) * 64 + row] = fmaxf(v.w + bs[4 * k4 + 3], 0.f);
    }
    __syncthreads();

    const int tr = tid & 15;
    const int tc = tid >> 4;

    float c[4][4];
    #pragma unroll
    for (int i = 0; i < 4; i++)
        #pragma unroll
        for (int j = 0; j < 4; j++) c[i][j] = 0.f;

    #pragma unroll 8
    for (int k = 0; k < 64; k++) {
        float4 a = *reinterpret_cast<const float4*>(hs + k * 64 + 4 * tr);
        float4 b = *reinterpret_cast<const float4*>(ws + k * 64 + 4 * tc);
        float av[4] = {a.x, a.y, a.z, a.w};
        float bv[4] = {b.x, b.y, b.z, b.w};
        #pragma unroll
        for (int i = 0; i < 4; i++)
            #pragma unroll
            for (int j = 0; j < 4; j++)
                c[i][j] = fmaf(av[i], bv[j], c[i][j]);
    }

    #pragma unroll
    for (int i = 0; i < 4; i++) {
        int gr = row0 + 4 * tr + i;
        if (gr < n) {
            float4 v = make_float4(c[i][0], c[i][1], c[i][2], c[i][3]);
            reinterpret_cast<float4*>(Y + (size_t)gr * HID)[tc] = v;
        }
    }
}

// ---------------------------------------------------------------------------
// kernel_launch
// Inputs: x, edge_row, edge_col, edge_val, W1, b1, W2, b2, lin_W, lin_b
// ---------------------------------------------------------------------------
extern "C" void kernel_launch(void* const* d_in, const int* in_sizes, int n_in,
                              void* d_out, int out_size)
{
    const float* x    = (const float*)d_in[0];
    const int*   erow = (const int*)  d_in[1];
    const int*   ecol = (const int*)  d_in[2];
    const float* eval = (const float*)d_in[3];
    const float* W1   = (const float*)d_in[4];
    const float* b1   = (const float*)d_in[5];
    const float* W2   = (const float*)d_in[6];
    const float* b2   = (const float*)d_in[7];
    const float* linW = (const float*)d_in[8];
    const float* linb = (const float*)d_in[9];
    float* out = (float*)d_out;

    const int n = in_sizes[0] / INF;
    const int E = in_sizes[1];

    float *buf0, *buf1;
    int *deg, *rptr, *wcur, *partial;
    int2 *cv;
    cudaGetSymbolAddress((void**)&buf0, g_buf0);
    cudaGetSymbolAddress((void**)&buf1, g_buf1);
    cudaGetSymbolAddress((void**)&deg,  g_deg);
    cudaGetSymbolAddress((void**)&rptr, g_rptr);
    cudaGetSymbolAddress((void**)&wcur, g_wcur);
    cudaGetSymbolAddress((void**)&cv,   g_cv);
    cudaGetSymbolAddress((void**)&partial, g_partial);

    static bool attr_done = false;
    if (!attr_done) {
        cudaFuncSetAttribute(gemm_in_kernel,
                             cudaFuncAttributeMaxDynamicSharedMemorySize, 65536);
        attr_done = true;
    }

    const int nb         = (n + 1023) / 1024;           // scan blocks (<=128)
    const int gemm_grid  = (n + 63) / 64;
    const int spmm_grid  = (n * 32 + 255) / 256;        // warp per row
    const int egrid      = 2048;

    // --- CSR build (once, used by both layers) ---
    zero_deg_kernel<<<256, 256>>>(deg, n);
    hist_kernel<<<egrid, 256>>>(erow, deg, E);
    partial_kernel<<<nb, 256>>>(deg, partial, n);
    scanp_kernel<<<1, 128>>>(partial, rptr, nb, n);
    scan_chunk_kernel<<<nb, 256>>>(deg, partial, rptr, wcur, n);
    scatter_kernel<<<egrid, 256>>>(erow, ecol, eval, wcur, cv, E);

    // --- Layer 1: buf0 = x@W1 ; buf1 = A@buf0 ---
    gemm_in_kernel<<<gemm_grid, 256, 65536>>>(x, W1, buf0, n);
    spmm_csr_kernel<<<spmm_grid, 256>>>(rptr, cv, buf0, buf1, n);

    // --- Layer 2: buf0 = relu(buf1+b1)@W2 ; out = head(A@buf0) ---
    gemm_hid_kernel<<<gemm_grid, 256>>>(buf1, b1, W2, buf0, n);
    spmm_csr_head_kernel<<<spmm_grid, 256>>>(rptr, cv, buf0, b2, linW, linb, out, n);
}

// round 3
// speedup vs baseline: 1.6902x; 1.1002x over previous
#include <cuda_runtime.h>
#include <cuda_fp16.h>
#include <cstdint>

// Problem constants (shapes fixed by the reference)
#define MAXN    100000
#define MAXE    3400000
#define INF     128
#define HID     64

// Scratch (device globals per allocation rules)
__device__ __half g_hA[(size_t)MAXN * HID];    // feature table A (12.8 MB)
__device__ __half g_hB[(size_t)MAXN * HID];    // feature table B (12.8 MB)
__device__ int   g_deg[MAXN];
__device__ int   g_rptr[MAXN + 1];
__device__ int   g_wcur[MAXN];
__device__ int2  g_cv[MAXE];                   // (col, val-bits) sorted by row
__device__ int   g_partial[256];

__device__ __forceinline__ uint32_t pack_h2(float a, float b) {
    __half2 h = __floats2half2_rn(a, b);
    return *reinterpret_cast<uint32_t*>(&h);
}

// ---------------------------------------------------------------------------
// CSR build: zero-deg, histogram, 3-pass scan, counting-sort scatter
// ---------------------------------------------------------------------------
__global__ void zero_deg_kernel(int* __restrict__ deg, int n) {
    int i = blockIdx.x * blockDim.x + threadIdx.x;
    for (; i < n; i += gridDim.x * blockDim.x) deg[i] = 0;
}

__global__ void hist_kernel(const int* __restrict__ erow, int* __restrict__ deg, int E) {
    int i = blockIdx.x * blockDim.x + threadIdx.x;
    for (; i < E; i += gridDim.x * blockDim.x)
        atomicAdd(deg + __ldg(erow + i), 1);
}

// block b sums deg[b*1024 .. b*1024+1023] -> partial[b]
__global__ __launch_bounds__(256) void partial_kernel(
    const int* __restrict__ deg, int* __restrict__ partial, int n)
{
    __shared__ int sh[256];
    int tid = threadIdx.x;
    int base = blockIdx.x * 1024 + tid * 4;
    int s = 0;
    #pragma unroll
    for (int j = 0; j < 4; j++) if (base + j < n) s += deg[base + j];
    sh[tid] = s; __syncthreads();
    for (int off = 128; off > 0; off >>= 1) {
        if (tid < off) sh[tid] += sh[tid + off];
        __syncthreads();
    }
    if (tid == 0) partial[blockIdx.x] = sh[0];
}

// exclusive scan of partials (nb <= 128)
__global__ __launch_bounds__(128) void scanp_kernel(
    int* __restrict__ partial, int* __restrict__ rptr, int nb, int n)
{
    __shared__ int sh[128];
    int tid = threadIdx.x;
    int v = (tid < nb) ? partial[tid] : 0;
    sh[tid] = v; __syncthreads();
    #pragma unroll
    for (int off = 1; off < 128; off <<= 1) {
        int y = (tid >= off) ? sh[tid - off] : 0;
        __syncthreads();
        sh[tid] += y;
        __syncthreads();
    }
    if (tid < nb) partial[tid] = sh[tid] - v;
    if (tid == 127) rptr[n] = sh[127];
}

// final scan: rptr[i] and wcur[i] = global exclusive prefix of deg
__global__ __launch_bounds__(256) void scan_chunk_kernel(
    const int* __restrict__ deg, const int* __restrict__ partial,
    int* __restrict__ rptr, int* __restrict__ wcur, int n)
{
    __shared__ int sh[256];
    int tid = threadIdx.x;
    int base = blockIdx.x * 1024 + tid * 4;
    int v[4]; int s = 0;
    #pragma unroll
    for (int j = 0; j < 4; j++) {
        v[j] = (base + j < n) ? deg[base + j] : 0;
        s += v[j];
    }
    sh[tid] = s; __syncthreads();
    #pragma unroll
    for (int off = 1; off < 256; off <<= 1) {
        int y = (tid >= off) ? sh[tid - off] : 0;
        __syncthreads();
        sh[tid] += y;
        __syncthreads();
    }
    int excl = sh[tid] - s + partial[blockIdx.x];
    #pragma unroll
    for (int j = 0; j < 4; j++) {
        if (base + j < n) { rptr[base + j] = excl; wcur[base + j] = excl; }
        excl += v[j];
    }
}

__global__ void scatter_kernel(
    const int* __restrict__ erow, const int* __restrict__ ecol,
    const float* __restrict__ eval,
    int* __restrict__ wcur, int2* __restrict__ cv, int E)
{
    int i = blockIdx.x * blockDim.x + threadIdx.x;
    for (; i < E; i += gridDim.x * blockDim.x) {
        int r = __ldg(erow + i);
        int p = atomicAdd(wcur + r, 1);
        cv[p] = make_int2(__ldg(ecol + i), __float_as_int(__ldg(eval + i)));
    }
}

// ---------------------------------------------------------------------------
// GEMM1: H[n,64] (fp16) = X[n,128] @ W[128,64]
// 64-row tile per block, 256 threads, 4x4 micro-tile. Dyn smem 64 KB.
// ---------------------------------------------------------------------------
__global__ __launch_bounds__(256) void gemm_in_kernel(
    const float* __restrict__ X, const float* __restrict__ W,
    __half* __restrict__ H, int n)
{
    extern __shared__ float sm[];
    float* xs = sm;               // [128][64] : xs[k*64 + r]
    float* ws = sm + 128 * 64;    // [128][64] : ws[k*64 + c]

    const int tid = threadIdx.x;
    const int row0 = blockIdx.x * 64;

    #pragma unroll
    for (int q = tid; q < 2048; q += 256)
        reinterpret_cast<float4*>(ws)[q] = reinterpret_cast<const float4*>(W)[q];

    #pragma unroll
    for (int it = 0; it < 8; it++) {
        int q   = tid + it * 256;
        int row = q & 63;
        int k4  = q >> 6;
        int gr  = row0 + row;
        float4 v = make_float4(0.f, 0.f, 0.f, 0.f);
        if (gr < n)
            v = reinterpret_cast<const float4*>(X + (size_t)gr * INF)[k4];
        xs[(4 * k4 + 0) * 64 + row] = v.x;
        xs[(4 * k4 + 1) * 64 + row] = v.y;
        xs[(4 * k4 + 2) * 64 + row] = v.z;
        xs[(4 * k4 + 3) * 64 + row] = v.w;
    }
    __syncthreads();

    const int tr = tid & 15;
    const int tc = tid >> 4;

    float c[4][4];
    #pragma unroll
    for (int i = 0; i < 4; i++)
        #pragma unroll
        for (int j = 0; j < 4; j++) c[i][j] = 0.f;

    #pragma unroll 8
    for (int k = 0; k < 128; k++) {
        float4 a = *reinterpret_cast<const float4*>(xs + k * 64 + 4 * tr);
        float4 b = *reinterpret_cast<const float4*>(ws + k * 64 + 4 * tc);
        float av[4] = {a.x, a.y, a.z, a.w};
        float bv[4] = {b.x, b.y, b.z, b.w};
        #pragma unroll
        for (int i = 0; i < 4; i++)
            #pragma unroll
            for (int j = 0; j < 4; j++)
                c[i][j] = fmaf(av[i], bv[j], c[i][j]);
    }

    #pragma unroll
    for (int i = 0; i < 4; i++) {
        int gr = row0 + 4 * tr + i;
        if (gr < n) {
            uint2 pv = make_uint2(pack_h2(c[i][0], c[i][1]),
                                  pack_h2(c[i][2], c[i][3]));
            reinterpret_cast<uint2*>(H + (size_t)gr * HID)[tc] = pv;
        }
    }
}

// ---------------------------------------------------------------------------
// SpMM layer-1: warp per dest row, fp16 gather, fp32 accum, epilogue
// relu(acc + b1) stored fp16.
// ---------------------------------------------------------------------------
__global__ __launch_bounds__(256) void spmm_relu_kernel(
    const int* __restrict__ rptr, const int2* __restrict__ cv,
    const __half* __restrict__ src, const float* __restrict__ b1,
    __half* __restrict__ dst, int n)
{
    int row  = (blockIdx.x * blockDim.x + threadIdx.x) >> 5;
    int lane = threadIdx.x & 31;
    if (row >= n) return;

    int s = __ldg(rptr + row);
    int e = __ldg(rptr + row + 1);
    float ax = 0.f, ay = 0.f;

    int i = s;
    for (; i + 4 <= e; i += 4) {
        int2 c0 = __ldg(cv + i), c1 = __ldg(cv + i + 1);
        int2 c2 = __ldg(cv + i + 2), c3 = __ldg(cv + i + 3);
        __half2 h0 = __ldg(reinterpret_cast<const __half2*>(src + (size_t)c0.x * HID) + lane);
        __half2 h1 = __ldg(reinterpret_cast<const __half2*>(src + (size_t)c1.x * HID) + lane);
        __half2 h2 = __ldg(reinterpret_cast<const __half2*>(src + (size_t)c2.x * HID) + lane);
        __half2 h3 = __ldg(reinterpret_cast<const __half2*>(src + (size_t)c3.x * HID) + lane);
        float2 s0 = __half22float2(h0), s1 = __half22float2(h1);
        float2 s2 = __half22float2(h2), s3 = __half22float2(h3);
        float v0 = __int_as_float(c0.y), v1 = __int_as_float(c1.y);
        float v2 = __int_as_float(c2.y), v3 = __int_as_float(c3.y);
        ax = fmaf(v0, s0.x, ax); ay = fmaf(v0, s0.y, ay);
        ax = fmaf(v1, s1.x, ax); ay = fmaf(v1, s1.y, ay);
        ax = fmaf(v2, s2.x, ax); ay = fmaf(v2, s2.y, ay);
        ax = fmaf(v3, s3.x, ax); ay = fmaf(v3, s3.y, ay);
    }
    for (; i < e; i++) {
        int2 c0 = __ldg(cv + i);
        __half2 h0 = __ldg(reinterpret_cast<const __half2*>(src + (size_t)c0.x * HID) + lane);
        float2 s0 = __half22float2(h0);
        float v0 = __int_as_float(c0.y);
        ax = fmaf(v0, s0.x, ax); ay = fmaf(v0, s0.y, ay);
    }

    float2 bb = __ldg(reinterpret_cast<const float2*>(b1) + lane);
    float a0 = fmaxf(ax + bb.x, 0.f);
    float a1 = fmaxf(ay + bb.y, 0.f);
    reinterpret_cast<uint32_t*>(dst + (size_t)row * HID)[lane] = pack_h2(a0, a1);
}

// ---------------------------------------------------------------------------
// SpMM layer-2 fused head: gather fp16, fp32 accum, relu(acc+b2).linW + linb
// ---------------------------------------------------------------------------
__global__ __launch_bounds__(256) void spmm_head_kernel(
    const int* __restrict__ rptr, const int2* __restrict__ cv,
    const __half* __restrict__ src,
    const float* __restrict__ b2, const float* __restrict__ linW,
    const float* __restrict__ linb, float* __restrict__ out, int n)
{
    int row  = (blockIdx.x * blockDim.x + threadIdx.x) >> 5;
    int lane = threadIdx.x & 31;
    if (row >= n) return;

    int s = __ldg(rptr + row);
    int e = __ldg(rptr + row + 1);
    float ax = 0.f, ay = 0.f;

    int i = s;
    for (; i + 4 <= e; i += 4) {
        int2 c0 = __ldg(cv + i), c1 = __ldg(cv + i + 1);
        int2 c2 = __ldg(cv + i + 2), c3 = __ldg(cv + i + 3);
        __half2 h0 = __ldg(reinterpret_cast<const __half2*>(src + (size_t)c0.x * HID) + lane);
        __half2 h1 = __ldg(reinterpret_cast<const __half2*>(src + (size_t)c1.x * HID) + lane);
        __half2 h2 = __ldg(reinterpret_cast<const __half2*>(src + (size_t)c2.x * HID) + lane);
        __half2 h3 = __ldg(reinterpret_cast<const __half2*>(src + (size_t)c3.x * HID) + lane);
        float2 s0 = __half22float2(h0), s1 = __half22float2(h1);
        float2 s2 = __half22float2(h2), s3 = __half22float2(h3);
        float v0 = __int_as_float(c0.y), v1 = __int_as_float(c1.y);
        float v2 = __int_as_float(c2.y), v3 = __int_as_float(c3.y);
        ax = fmaf(v0, s0.x, ax); ay = fmaf(v0, s0.y, ay);
        ax = fmaf(v1, s1.x, ax); ay = fmaf(v1, s1.y, ay);
        ax = fmaf(v2, s2.x, ax); ay = fmaf(v2, s2.y, ay);
        ax = fmaf(v3, s3.x, ax); ay = fmaf(v3, s3.y, ay);
    }
    for (; i < e; i++) {
        int2 c0 = __ldg(cv + i);
        __half2 h0 = __ldg(reinterpret_cast<const __half2*>(src + (size_t)c0.x * HID) + lane);
        float2 s0 = __half22float2(h0);
        float v0 = __int_as_float(c0.y);
        ax = fmaf(v0, s0.x, ax); ay = fmaf(v0, s0.y, ay);
    }

    float2 bb = __ldg(reinterpret_cast<const float2*>(b2) + lane);
    float2 ww = __ldg(reinterpret_cast<const float2*>(linW) + lane);
    float a0 = fmaxf(ax + bb.x, 0.f);
    float a1 = fmaxf(ay + bb.y, 0.f);
    float sum = a0 * ww.x + a1 * ww.y;
    #pragma unroll
    for (int o = 16; o > 0; o >>= 1)
        sum += __shfl_xor_sync(0xFFFFFFFFu, sum, o);
    if (lane == 0) out[row] = sum + __ldg(linb);
}

// ---------------------------------------------------------------------------
// GEMM2: H2[n,64] (fp16) = H1[n,64] (fp16, bias/relu already applied) @ W2
// ---------------------------------------------------------------------------
__global__ __launch_bounds__(256) void gemm_hid_kernel(
    const __half* __restrict__ Hin, const float* __restrict__ W2,
    __half* __restrict__ Hout, int n)
{
    __shared__ float hs[64 * 64];   // hs[k*64 + r]
    __shared__ float ws[64 * 64];   // ws[k*64 + c]

    const int tid = threadIdx.x;
    const int row0 = blockIdx.x * 64;

    #pragma unroll
    for (int q = tid; q < 1024; q += 256)
        reinterpret_cast<float4*>(ws)[q] = reinterpret_cast<const float4*>(W2)[q];

    // H tile: 1024 uint2 chunks (4 halfs each); q -> (row = q%64, k4 = q/64)
    #pragma unroll
    for (int it = 0; it < 4; it++) {
        int q   = tid + it * 256;
        int row = q & 63;
        int k4  = q >> 6;       // 0..15
        int gr  = row0 + row;
        uint2 raw = make_uint2(0u, 0u);
        if (gr < n)
            raw = reinterpret_cast<const uint2*>(Hin + (size_t)gr * HID)[k4];
        __half2 h0 = *reinterpret_cast<__half2*>(&raw.x);
        __half2 h1 = *reinterpret_cast<__half2*>(&raw.y);
        float2 f0 = __half22float2(h0);
        float2 f1 = __half22float2(h1);
        hs[(4 * k4 + 0) * 64 + row] = f0.x;
        hs[(4 * k4 + 1) * 64 + row] = f0.y;
        hs[(4 * k4 + 2) * 64 + row] = f1.x;
        hs[(4 * k4 + 3) * 64 + row] = f1.y;
    }
    __syncthreads();

    const int tr = tid & 15;
    const int tc = tid >> 4;

    float c[4][4];
    #pragma unroll
    for (int i = 0; i < 4; i++)
        #pragma unroll
        for (int j = 0; j < 4; j++) c[i][j] = 0.f;

    #pragma unroll 8
    for (int k = 0; k < 64; k++) {
        float4 a = *reinterpret_cast<const float4*>(hs + k * 64 + 4 * tr);
        float4 b = *reinterpret_cast<const float4*>(ws + k * 64 + 4 * tc);
        float av[4] = {a.x, a.y, a.z, a.w};
        float bv[4] = {b.x, b.y, b.z, b.w};
        #pragma unroll
        for (int i = 0; i < 4; i++)
            #pragma unroll
            for (int j = 0; j < 4; j++)
                c[i][j] = fmaf(av[i], bv[j], c[i][j]);
    }

    #pragma unroll
    for (int i = 0; i < 4; i++) {
        int gr = row0 + 4 * tr + i;
        if (gr < n) {
            uint2 pv = make_uint2(pack_h2(c[i][0], c[i][1]),
                                  pack_h2(c[i][2], c[i][3]));
            reinterpret_cast<uint2*>(Hout + (size_t)gr * HID)[tc] = pv;
        }
    }
}

// ---------------------------------------------------------------------------
// kernel_launch
// Inputs: x, edge_row, edge_col, edge_val, W1, b1, W2, b2, lin_W, lin_b
// ---------------------------------------------------------------------------
extern "C" void kernel_launch(void* const* d_in, const int* in_sizes, int n_in,
                              void* d_out, int out_size)
{
    const float* x    = (const float*)d_in[0];
    const int*   erow = (const int*)  d_in[1];
    const int*   ecol = (const int*)  d_in[2];
    const float* eval = (const float*)d_in[3];
    const float* W1   = (const float*)d_in[4];
    const float* b1   = (const float*)d_in[5];
    const float* W2   = (const float*)d_in[6];
    const float* b2   = (const float*)d_in[7];
    const float* linW = (const float*)d_in[8];
    const float* linb = (const float*)d_in[9];
    float* out = (float*)d_out;

    const int n = in_sizes[0] / INF;
    const int E = in_sizes[1];

    __half *hA, *hB;
    int *deg, *rptr, *wcur, *partial;
    int2 *cv;
    cudaGetSymbolAddress((void**)&hA,   g_hA);
    cudaGetSymbolAddress((void**)&hB,   g_hB);
    cudaGetSymbolAddress((void**)&deg,  g_deg);
    cudaGetSymbolAddress((void**)&rptr, g_rptr);
    cudaGetSymbolAddress((void**)&wcur, g_wcur);
    cudaGetSymbolAddress((void**)&cv,   g_cv);
    cudaGetSymbolAddress((void**)&partial, g_partial);

    static bool init_done = false;
    static cudaStream_t side = nullptr;
    static cudaEvent_t evFork = nullptr, evJoin = nullptr;
    if (!init_done) {
        cudaFuncSetAttribute(gemm_in_kernel,
                             cudaFuncAttributeMaxDynamicSharedMemorySize, 65536);
        cudaStreamCreateWithFlags(&side, cudaStreamNonBlocking);
        cudaEventCreateWithFlags(&evFork, cudaEventDisableTiming);
        cudaEventCreateWithFlags(&evJoin, cudaEventDisableTiming);
        init_done = true;
    }

    const int nb         = (n + 1023) / 1024;     // scan blocks (<=128)
    const int gemm_grid  = (n + 63) / 64;
    const int spmm_grid  = (n * 32 + 255) / 256;  // warp per row
    const int egrid      = 2048;

    // --- Fork: CSR build on side stream, overlapped with GEMM1 ---
    cudaEventRecord(evFork, 0);
    cudaStreamWaitEvent(side, evFork, 0);
    zero_deg_kernel<<<256, 256, 0, side>>>(deg, n);
    hist_kernel<<<egrid, 256, 0, side>>>(erow, deg, E);
    partial_kernel<<<nb, 256, 0, side>>>(deg, partial, n);
    scanp_kernel<<<1, 128, 0, side>>>(partial, rptr, nb, n);
    scan_chunk_kernel<<<nb, 256, 0, side>>>(deg, partial, rptr, wcur, n);
    scatter_kernel<<<egrid, 256, 0, side>>>(erow, ecol, eval, wcur, cv, E);
    cudaEventRecord(evJoin, side);

    // --- GEMM1 on main stream (concurrent with build) ---
    gemm_in_kernel<<<gemm_grid, 256, 65536>>>(x, W1, hA, n);

    // --- Join, then layer-1 SpMM (+bias1+relu): hB = relu(A@hA + b1) ---
    cudaStreamWaitEvent(0, evJoin, 0);
    spmm_relu_kernel<<<spmm_grid, 256>>>(rptr, cv, hA, b1, hB, n);

    // --- Layer 2: hA = hB @ W2 ; out = head(A@hA) ---
    gemm_hid_kernel<<<gemm_grid, 256>>>(hB, W2, hA, n);
    spmm_head_kernel<<<spmm_grid, 256>>>(rptr, cv, hA, b2, linW, linb, out, n);
}

// round 4
// speedup vs baseline: 1.7530x; 1.0372x over previous
#include <cuda_runtime.h>
#include <cuda_fp16.h>
#include <cstdint>

// Problem constants (shapes fixed by the reference)
#define MAXN    100000
#define MAXE    3400000
#define INF     128
#define HID     64

// Scratch (device globals per allocation rules)
__device__ __half g_hA[(size_t)MAXN * HID];    // feature table A (12.8 MB)
__device__ __half g_hB[(size_t)MAXN * HID];    // feature table B (12.8 MB)
__device__ int   g_deg[MAXN];
__device__ int   g_rptr[MAXN + 1];
__device__ int   g_wcur[MAXN];
__device__ int2  g_cv[MAXE];                   // (col, val-bits) sorted by row
__device__ int   g_partial[256];

__device__ __forceinline__ uint32_t pack_h2(float a, float b) {
    __half2 h = __floats2half2_rn(a, b);
    return *reinterpret_cast<uint32_t*>(&h);
}

// ---------------------------------------------------------------------------
// CSR build: zero-deg, histogram, 3-pass scan, counting-sort scatter
// ---------------------------------------------------------------------------
__global__ void zero_deg_kernel(int* __restrict__ deg, int n) {
    int i = blockIdx.x * blockDim.x + threadIdx.x;
    for (; i < n; i += gridDim.x * blockDim.x) deg[i] = 0;
}

__global__ void hist_kernel(const int* __restrict__ erow, int* __restrict__ deg, int E) {
    int i = blockIdx.x * blockDim.x + threadIdx.x;
    for (; i < E; i += gridDim.x * blockDim.x)
        atomicAdd(deg + __ldg(erow + i), 1);
}

__global__ __launch_bounds__(256) void partial_kernel(
    const int* __restrict__ deg, int* __restrict__ partial, int n)
{
    __shared__ int sh[256];
    int tid = threadIdx.x;
    int base = blockIdx.x * 1024 + tid * 4;
    int s = 0;
    #pragma unroll
    for (int j = 0; j < 4; j++) if (base + j < n) s += deg[base + j];
    sh[tid] = s; __syncthreads();
    for (int off = 128; off > 0; off >>= 1) {
        if (tid < off) sh[tid] += sh[tid + off];
        __syncthreads();
    }
    if (tid == 0) partial[blockIdx.x] = sh[0];
}

__global__ __launch_bounds__(128) void scanp_kernel(
    int* __restrict__ partial, int* __restrict__ rptr, int nb, int n)
{
    __shared__ int sh[128];
    int tid = threadIdx.x;
    int v = (tid < nb) ? partial[tid] : 0;
    sh[tid] = v; __syncthreads();
    #pragma unroll
    for (int off = 1; off < 128; off <<= 1) {
        int y = (tid >= off) ? sh[tid - off] : 0;
        __syncthreads();
        sh[tid] += y;
        __syncthreads();
    }
    if (tid < nb) partial[tid] = sh[tid] - v;
    if (tid == 127) rptr[n] = sh[127];
}

__global__ __launch_bounds__(256) void scan_chunk_kernel(
    const int* __restrict__ deg, const int* __restrict__ partial,
    int* __restrict__ rptr, int* __restrict__ wcur, int n)
{
    __shared__ int sh[256];
    int tid = threadIdx.x;
    int base = blockIdx.x * 1024 + tid * 4;
    int v[4]; int s = 0;
    #pragma unroll
    for (int j = 0; j < 4; j++) {
        v[j] = (base + j < n) ? deg[base + j] : 0;
        s += v[j];
    }
    sh[tid] = s; __syncthreads();
    #pragma unroll
    for (int off = 1; off < 256; off <<= 1) {
        int y = (tid >= off) ? sh[tid - off] : 0;
        __syncthreads();
        sh[tid] += y;
        __syncthreads();
    }
    int excl = sh[tid] - s + partial[blockIdx.x];
    #pragma unroll
    for (int j = 0; j < 4; j++) {
        if (base + j < n) { rptr[base + j] = excl; wcur[base + j] = excl; }
        excl += v[j];
    }
}

__global__ void scatter_kernel(
    const int* __restrict__ erow, const int* __restrict__ ecol,
    const float* __restrict__ eval,
    int* __restrict__ wcur, int2* __restrict__ cv, int E)
{
    int i = blockIdx.x * blockDim.x + threadIdx.x;
    for (; i < E; i += gridDim.x * blockDim.x) {
        int r = __ldg(erow + i);
        int p = atomicAdd(wcur + r, 1);
        cv[p] = make_int2(__ldg(ecol + i), __float_as_int(__ldg(eval + i)));
    }
}

// ---------------------------------------------------------------------------
// GEMM1: H[n,64] (fp16) = X[n,128] @ W[128,64]
// ---------------------------------------------------------------------------
__global__ __launch_bounds__(256) void gemm_in_kernel(
    const float* __restrict__ X, const float* __restrict__ W,
    __half* __restrict__ H, int n)
{
    extern __shared__ float sm[];
    float* xs = sm;               // [128][64] : xs[k*64 + r]
    float* ws = sm + 128 * 64;    // [128][64] : ws[k*64 + c]

    const int tid = threadIdx.x;
    const int row0 = blockIdx.x * 64;

    #pragma unroll
    for (int q = tid; q < 2048; q += 256)
        reinterpret_cast<float4*>(ws)[q] = reinterpret_cast<const float4*>(W)[q];

    #pragma unroll
    for (int it = 0; it < 8; it++) {
        int q   = tid + it * 256;
        int row = q & 63;
        int k4  = q >> 6;
        int gr  = row0 + row;
        float4 v = make_float4(0.f, 0.f, 0.f, 0.f);
        if (gr < n)
            v = reinterpret_cast<const float4*>(X + (size_t)gr * INF)[k4];
        xs[(4 * k4 + 0) * 64 + row] = v.x;
        xs[(4 * k4 + 1) * 64 + row] = v.y;
        xs[(4 * k4 + 2) * 64 + row] = v.z;
        xs[(4 * k4 + 3) * 64 + row] = v.w;
    }
    __syncthreads();

    const int tr = tid & 15;
    const int tc = tid >> 4;

    float c[4][4];
    #pragma unroll
    for (int i = 0; i < 4; i++)
        #pragma unroll
        for (int j = 0; j < 4; j++) c[i][j] = 0.f;

    #pragma unroll 8
    for (int k = 0; k < 128; k++) {
        float4 a = *reinterpret_cast<const float4*>(xs + k * 64 + 4 * tr);
        float4 b = *reinterpret_cast<const float4*>(ws + k * 64 + 4 * tc);
        float av[4] = {a.x, a.y, a.z, a.w};
        float bv[4] = {b.x, b.y, b.z, b.w};
        #pragma unroll
        for (int i = 0; i < 4; i++)
            #pragma unroll
            for (int j = 0; j < 4; j++)
                c[i][j] = fmaf(av[i], bv[j], c[i][j]);
    }

    #pragma unroll
    for (int i = 0; i < 4; i++) {
        int gr = row0 + 4 * tr + i;
        if (gr < n) {
            uint2 pv = make_uint2(pack_h2(c[i][0], c[i][1]),
                                  pack_h2(c[i][2], c[i][3]));
            reinterpret_cast<uint2*>(H + (size_t)gr * HID)[tc] = pv;
        }
    }
}

// ---------------------------------------------------------------------------
// SpMM core: warp per dest row; 4 edges per gather instruction.
// lane = (g = lane>>3, q = lane&7). One LDG.128 fetches 16B x 32 lanes = the
// full 128B rows of 4 edges. Accumulate 8 features/lane in fp32; combine the
// 4 edge-groups with 2 rounds of shfl_xor at the end.
// ---------------------------------------------------------------------------
#define SPMM_BODY                                                              \
    int g = lane >> 3;                                                         \
    int q = lane & 7;                                                          \
    int s = __ldg(rptr + row);                                                 \
    int e = __ldg(rptr + row + 1);                                             \
    float2 a0 = make_float2(0.f, 0.f), a1 = make_float2(0.f, 0.f);             \
    float2 a2 = make_float2(0.f, 0.f), a3 = make_float2(0.f, 0.f);             \
    for (int i = s; i < e; i += 8) {                                           \
        int  iA = i + g,      iB = i + 4 + g;                                  \
        bool vA = iA < e,     vB = iB < e;                                     \
        int2 cA = __ldg(cv + (vA ? iA : s));                                   \
        int2 cB = __ldg(cv + (vB ? iB : s));                                   \
        float wA = vA ? __int_as_float(cA.y) : 0.f;                            \
        float wB = vB ? __int_as_float(cB.y) : 0.f;                            \
        uint4 rA = __ldg(reinterpret_cast<const uint4*>(src + (size_t)cA.x * HID) + q); \
        uint4 rB = __ldg(reinterpret_cast<const uint4*>(src + (size_t)cB.x * HID) + q); \
        float2 f;                                                              \
        f = __half22float2(*reinterpret_cast<__half2*>(&rA.x));                \
        a0.x = fmaf(wA, f.x, a0.x); a0.y = fmaf(wA, f.y, a0.y);                \
        f = __half22float2(*reinterpret_cast<__half2*>(&rA.y));                \
        a1.x = fmaf(wA, f.x, a1.x); a1.y = fmaf(wA, f.y, a1.y);                \
        f = __half22float2(*reinterpret_cast<__half2*>(&rA.z));                \
        a2.x = fmaf(wA, f.x, a2.x); a2.y = fmaf(wA, f.y, a2.y);                \
        f = __half22float2(*reinterpret_cast<__half2*>(&rA.w));                \
        a3.x = fmaf(wA, f.x, a3.x); a3.y = fmaf(wA, f.y, a3.y);                \
        f = __half22float2(*reinterpret_cast<__half2*>(&rB.x));                \
        a0.x = fmaf(wB, f.x, a0.x); a0.y = fmaf(wB, f.y, a0.y);                \
        f = __half22float2(*reinterpret_cast<__half2*>(&rB.y));                \
        a1.x = fmaf(wB, f.x, a1.x); a1.y = fmaf(wB, f.y, a1.y);                \
        f = __half22float2(*reinterpret_cast<__half2*>(&rB.z));                \
        a2.x = fmaf(wB, f.x, a2.x); a2.y = fmaf(wB, f.y, a2.y);                \
        f = __half22float2(*reinterpret_cast<__half2*>(&rB.w));                \
        a3.x = fmaf(wB, f.x, a3.x); a3.y = fmaf(wB, f.y, a3.y);                \
    }                                                                          \
    _Pragma("unroll")                                                          \
    for (int off = 8; off <= 16; off <<= 1) {                                  \
        a0.x += __shfl_xor_sync(0xFFFFFFFFu, a0.x, off);                       \
        a0.y += __shfl_xor_sync(0xFFFFFFFFu, a0.y, off);                       \
        a1.x += __shfl_xor_sync(0xFFFFFFFFu, a1.x, off);                       \
        a1.y += __shfl_xor_sync(0xFFFFFFFFu, a1.y, off);                       \
        a2.x += __shfl_xor_sync(0xFFFFFFFFu, a2.x, off);                       \
        a2.y += __shfl_xor_sync(0xFFFFFFFFu, a2.y, off);                       \
        a3.x += __shfl_xor_sync(0xFFFFFFFFu, a3.x, off);                       \
        a3.y += __shfl_xor_sync(0xFFFFFFFFu, a3.y, off);                       \
    }

// Layer-1 SpMM: epilogue relu(acc + b1), store fp16 row (lanes 0-7 store uint4)
__global__ __launch_bounds__(256) void spmm_relu_kernel(
    const int* __restrict__ rptr, const int2* __restrict__ cv,
    const __half* __restrict__ src, const float* __restrict__ b1,
    __half* __restrict__ dst, int n)
{
    int row  = (blockIdx.x * blockDim.x + threadIdx.x) >> 5;
    int lane = threadIdx.x & 31;
    if (row >= n) return;

    SPMM_BODY

    if (g == 0) {
        float4 bA = __ldg(reinterpret_cast<const float4*>(b1) + 2 * q);
        float4 bB = __ldg(reinterpret_cast<const float4*>(b1) + 2 * q + 1);
        float r0 = fmaxf(a0.x + bA.x, 0.f), r1 = fmaxf(a0.y + bA.y, 0.f);
        float r2 = fmaxf(a1.x + bA.z, 0.f), r3 = fmaxf(a1.y + bA.w, 0.f);
        float r4 = fmaxf(a2.x + bB.x, 0.f), r5 = fmaxf(a2.y + bB.y, 0.f);
        float r6 = fmaxf(a3.x + bB.z, 0.f), r7 = fmaxf(a3.y + bB.w, 0.f);
        uint4 pv = make_uint4(pack_h2(r0, r1), pack_h2(r2, r3),
                              pack_h2(r4, r5), pack_h2(r6, r7));
        reinterpret_cast<uint4*>(dst + (size_t)row * HID)[q] = pv;
    }
}

// Layer-2 SpMM fused head: relu(acc + b2) . linW, + linb -> out[row]
__global__ __launch_bounds__(256) void spmm_head_kernel(
    const int* __restrict__ rptr, const int2* __restrict__ cv,
    const __half* __restrict__ src,
    const float* __restrict__ b2, const float* __restrict__ linW,
    const float* __restrict__ linb, float* __restrict__ out, int n)
{
    int row  = (blockIdx.x * blockDim.x + threadIdx.x) >> 5;
    int lane = threadIdx.x & 31;
    if (row >= n) return;

    SPMM_BODY

    float4 bA = __ldg(reinterpret_cast<const float4*>(b2) + 2 * q);
    float4 bB = __ldg(reinterpret_cast<const float4*>(b2) + 2 * q + 1);
    float4 wA = __ldg(reinterpret_cast<const float4*>(linW) + 2 * q);
    float4 wB = __ldg(reinterpret_cast<const float4*>(linW) + 2 * q + 1);
    float sum = fmaxf(a0.x + bA.x, 0.f) * wA.x + fmaxf(a0.y + bA.y, 0.f) * wA.y
              + fmaxf(a1.x + bA.z, 0.f) * wA.z + fmaxf(a1.y + bA.w, 0.f) * wA.w
              + fmaxf(a2.x + bB.x, 0.f) * wB.x + fmaxf(a2.y + bB.y, 0.f) * wB.y
              + fmaxf(a3.x + bB.z, 0.f) * wB.z + fmaxf(a3.y + bB.w, 0.f) * wB.w;
    #pragma unroll
    for (int off = 1; off <= 4; off <<= 1)
        sum += __shfl_xor_sync(0xFFFFFFFFu, sum, off);
    if (lane == 0) out[row] = sum + __ldg(linb);
}

// ---------------------------------------------------------------------------
// GEMM2: H2[n,64] (fp16) = H1[n,64] (fp16, bias/relu already applied) @ W2
// ---------------------------------------------------------------------------
__global__ __launch_bounds__(256) void gemm_hid_kernel(
    const __half* __restrict__ Hin, const float* __restrict__ W2,
    __half* __restrict__ Hout, int n)
{
    __shared__ float hs[64 * 64];   // hs[k*64 + r]
    __shared__ float ws[64 * 64];   // ws[k*64 + c]

    const int tid = threadIdx.x;
    const int row0 = blockIdx.x * 64;

    #pragma unroll
    for (int q = tid; q < 1024; q += 256)
        reinterpret_cast<float4*>(ws)[q] = reinterpret_cast<const float4*>(W2)[q];

    #pragma unroll
    for (int it = 0; it < 4; it++) {
        int q   = tid + it * 256;
        int row = q & 63;
        int k4  = q >> 6;
        int gr  = row0 + row;
        uint2 raw = make_uint2(0u, 0u);
        if (gr < n)
            raw = reinterpret_cast<const uint2*>(Hin + (size_t)gr * HID)[k4];
        __half2 h0 = *reinterpret_cast<__half2*>(&raw.x);
        __half2 h1 = *reinterpret_cast<__half2*>(&raw.y);
        float2 f0 = __half22float2(h0);
        float2 f1 = __half22float2(h1);
        hs[(4 * k4 + 0) * 64 + row] = f0.x;
        hs[(4 * k4 + 1) * 64 + row] = f0.y;
        hs[(4 * k4 + 2) * 64 + row] = f1.x;
        hs[(4 * k4 + 3) * 64 + row] = f1.y;
    }
    __syncthreads();

    const int tr = tid & 15;
    const int tc = tid >> 4;

    float c[4][4];
    #pragma unroll
    for (int i = 0; i < 4; i++)
        #pragma unroll
        for (int j = 0; j < 4; j++) c[i][j] = 0.f;

    #pragma unroll 8
    for (int k = 0; k < 64; k++) {
        float4 a = *reinterpret_cast<const float4*>(hs + k * 64 + 4 * tr);
        float4 b = *reinterpret_cast<const float4*>(ws + k * 64 + 4 * tc);
        float av[4] = {a.x, a.y, a.z, a.w};
        float bv[4] = {b.x, b.y, b.z, b.w};
        #pragma unroll
        for (int i = 0; i < 4; i++)
            #pragma unroll
            for (int j = 0; j < 4; j++)
                c[i][j] = fmaf(av[i], bv[j], c[i][j]);
    }

    #pragma unroll
    for (int i = 0; i < 4; i++) {
        int gr = row0 + 4 * tr + i;
        if (gr < n) {
            uint2 pv = make_uint2(pack_h2(c[i][0], c[i][1]),
                                  pack_h2(c[i][2], c[i][3]));
            reinterpret_cast<uint2*>(Hout + (size_t)gr * HID)[tc] = pv;
        }
    }
}

// ---------------------------------------------------------------------------
// kernel_launch
// Inputs: x, edge_row, edge_col, edge_val, W1, b1, W2, b2, lin_W, lin_b
// ---------------------------------------------------------------------------
extern "C" void kernel_launch(void* const* d_in, const int* in_sizes, int n_in,
                              void* d_out, int out_size)
{
    const float* x    = (const float*)d_in[0];
    const int*   erow = (const int*)  d_in[1];
    const int*   ecol = (const int*)  d_in[2];
    const float* eval = (const float*)d_in[3];
    const float* W1   = (const float*)d_in[4];
    const float* b1   = (const float*)d_in[5];
    const float* W2   = (const float*)d_in[6];
    const float* b2   = (const float*)d_in[7];
    const float* linW = (const float*)d_in[8];
    const float* linb = (const float*)d_in[9];
    float* out = (float*)d_out;

    const int n = in_sizes[0] / INF;
    const int E = in_sizes[1];

    __half *hA, *hB;
    int *deg, *rptr, *wcur, *partial;
    int2 *cv;
    cudaGetSymbolAddress((void**)&hA,   g_hA);
    cudaGetSymbolAddress((void**)&hB,   g_hB);
    cudaGetSymbolAddress((void**)&deg,  g_deg);
    cudaGetSymbolAddress((void**)&rptr, g_rptr);
    cudaGetSymbolAddress((void**)&wcur, g_wcur);
    cudaGetSymbolAddress((void**)&cv,   g_cv);
    cudaGetSymbolAddress((void**)&partial, g_partial);

    static bool init_done = false;
    static cudaStream_t side = nullptr;
    static cudaEvent_t evFork = nullptr, evJoin = nullptr;
    if (!init_done) {
        cudaFuncSetAttribute(gemm_in_kernel,
                             cudaFuncAttributeMaxDynamicSharedMemorySize, 65536);
        cudaStreamCreateWithFlags(&side, cudaStreamNonBlocking);
        cudaEventCreateWithFlags(&evFork, cudaEventDisableTiming);
        cudaEventCreateWithFlags(&evJoin, cudaEventDisableTiming);
        init_done = true;
    }

    const int nb         = (n + 1023) / 1024;     // scan blocks (<=128)
    const int gemm_grid  = (n + 63) / 64;
    const int spmm_grid  = (n * 32 + 255) / 256;  // warp per row
    const int egrid      = 2048;

    // --- Fork: CSR build on side stream, overlapped with GEMM1 ---
    cudaEventRecord(evFork, 0);
    cudaStreamWaitEvent(side, evFork, 0);
    zero_deg_kernel<<<256, 256, 0, side>>>(deg, n);
    hist_kernel<<<egrid, 256, 0, side>>>(erow, deg, E);
    partial_kernel<<<nb, 256, 0, side>>>(deg, partial, n);
    scanp_kernel<<<1, 128, 0, side>>>(partial, rptr, nb, n);
    scan_chunk_kernel<<<nb, 256, 0, side>>>(deg, partial, rptr, wcur, n);
    scatter_kernel<<<egrid, 256, 0, side>>>(erow, ecol, eval, wcur, cv, E);
    cudaEventRecord(evJoin, side);

    // --- GEMM1 on main stream (concurrent with build) ---
    gemm_in_kernel<<<gemm_grid, 256, 65536>>>(x, W1, hA, n);

    // --- Join, then layer-1 SpMM (+bias1+relu): hB = relu(A@hA + b1) ---
    cudaStreamWaitEvent(0, evJoin, 0);
    spmm_relu_kernel<<<spmm_grid, 256>>>(rptr, cv, hA, b1, hB, n);

    // --- Layer 2: hA = hB @ W2 ; out = head(A@hA) ---
    gemm_hid_kernel<<<gemm_grid, 256>>>(hB, W2, hA, n);
    spmm_head_kernel<<<spmm_grid, 256>>>(rptr, cv, hA, b2, linW, linb, out, n);
}

// round 5
// speedup vs baseline: 2.1685x; 1.2370x over previous
#include <cuda_runtime.h>
#include <cuda_fp16.h>
#include <cstdint>

// Problem constants (shapes fixed by the reference)
#define MAXN    100000
#define MAXE    3400000
#define INF     128
#define HID     64

// Scratch (device globals per allocation rules)
__device__ __half g_hA[(size_t)MAXN * HID];    // feature table A (12.8 MB)
__device__ __half g_hB[(size_t)MAXN * HID];    // feature table B (12.8 MB)
__device__ __half g_w1t[64 * 128];             // W1^T (n-major) fp16
__device__ __half g_w2t[64 * 64];              // W2^T (n-major) fp16
__device__ int   g_deg[MAXN];
__device__ int   g_rptr[MAXN + 1];
__device__ int   g_wcur[MAXN];
__device__ int2  g_cv[MAXE];                   // (col, val-bits) sorted by row
__device__ int   g_partial[256];

__device__ __forceinline__ uint32_t pack_h2(float a, float b) {
    __half2 h = __floats2half2_rn(a, b);
    return *reinterpret_cast<uint32_t*>(&h);
}

// m16n8k16 fp16 MMA, fp32 accum, in-place C
__device__ __forceinline__ void mma16816(float* c,
    uint32_t a0, uint32_t a1, uint32_t a2, uint32_t a3,
    uint32_t b0, uint32_t b1)
{
    asm volatile(
        "mma.sync.aligned.m16n8k16.row.col.f32.f16.f16.f32 "
        "{%0,%1,%2,%3}, {%4,%5,%6,%7}, {%8,%9}, {%0,%1,%2,%3};\n"
        : "+f"(c[0]), "+f"(c[1]), "+f"(c[2]), "+f"(c[3])
        : "r"(a0), "r"(a1), "r"(a2), "r"(a3), "r"(b0), "r"(b1));
}

// ---------------------------------------------------------------------------
// Weight transpose + fp16 convert: Wt[n][k] = W[k][n]
// ---------------------------------------------------------------------------
__global__ void wconv_kernel(const float* __restrict__ W1,
                             const float* __restrict__ W2,
                             __half* __restrict__ Wt1, __half* __restrict__ Wt2)
{
    int i = blockIdx.x * blockDim.x + threadIdx.x;
    if (i < 64 * 128) {
        int nn = i >> 7, k = i & 127;
        Wt1[i] = __float2half(W1[k * 64 + nn]);
    }
    int j = i - 64 * 128;
    if (j >= 0 && j < 64 * 64) {
        int nn = j >> 6, k = j & 63;
        Wt2[j] = __float2half(W2[k * 64 + nn]);
    }
}

// ---------------------------------------------------------------------------
// CSR build: zero-deg, histogram, 3-pass scan, counting-sort scatter
// ---------------------------------------------------------------------------
__global__ void zero_deg_kernel(int* __restrict__ deg, int n) {
    int i = blockIdx.x * blockDim.x + threadIdx.x;
    for (; i < n; i += gridDim.x * blockDim.x) deg[i] = 0;
}

__global__ void hist_kernel(const int* __restrict__ erow, int* __restrict__ deg, int E) {
    int i = blockIdx.x * blockDim.x + threadIdx.x;
    for (; i < E; i += gridDim.x * blockDim.x)
        atomicAdd(deg + __ldg(erow + i), 1);
}

__global__ __launch_bounds__(256) void partial_kernel(
    const int* __restrict__ deg, int* __restrict__ partial, int n)
{
    __shared__ int sh[256];
    int tid = threadIdx.x;
    int base = blockIdx.x * 1024 + tid * 4;
    int s = 0;
    #pragma unroll
    for (int j = 0; j < 4; j++) if (base + j < n) s += deg[base + j];
    sh[tid] = s; __syncthreads();
    for (int off = 128; off > 0; off >>= 1) {
        if (tid < off) sh[tid] += sh[tid + off];
        __syncthreads();
    }
    if (tid == 0) partial[blockIdx.x] = sh[0];
}

__global__ __launch_bounds__(128) void scanp_kernel(
    int* __restrict__ partial, int* __restrict__ rptr, int nb, int n)
{
    __shared__ int sh[128];
    int tid = threadIdx.x;
    int v = (tid < nb) ? partial[tid] : 0;
    sh[tid] = v; __syncthreads();
    #pragma unroll
    for (int off = 1; off < 128; off <<= 1) {
        int y = (tid >= off) ? sh[tid - off] : 0;
        __syncthreads();
        sh[tid] += y;
        __syncthreads();
    }
    if (tid < nb) partial[tid] = sh[tid] - v;
    if (tid == 127) rptr[n] = sh[127];
}

__global__ __launch_bounds__(256) void scan_chunk_kernel(
    const int* __restrict__ deg, const int* __restrict__ partial,
    int* __restrict__ rptr, int* __restrict__ wcur, int n)
{
    __shared__ int sh[256];
    int tid = threadIdx.x;
    int base = blockIdx.x * 1024 + tid * 4;
    int v[4]; int s = 0;
    #pragma unroll
    for (int j = 0; j < 4; j++) {
        v[j] = (base + j < n) ? deg[base + j] : 0;
        s += v[j];
    }
    sh[tid] = s; __syncthreads();
    #pragma unroll
    for (int off = 1; off < 256; off <<= 1) {
        int y = (tid >= off) ? sh[tid - off] : 0;
        __syncthreads();
        sh[tid] += y;
        __syncthreads();
    }
    int excl = sh[tid] - s + partial[blockIdx.x];
    #pragma unroll
    for (int j = 0; j < 4; j++) {
        if (base + j < n) { rptr[base + j] = excl; wcur[base + j] = excl; }
        excl += v[j];
    }
}

__global__ void scatter_kernel(
    const int* __restrict__ erow, const int* __restrict__ ecol,
    const float* __restrict__ eval,
    int* __restrict__ wcur, int2* __restrict__ cv, int E)
{
    int i = blockIdx.x * blockDim.x + threadIdx.x;
    for (; i < E; i += gridDim.x * blockDim.x) {
        int r = __ldg(erow + i);
        int p = atomicAdd(wcur + r, 1);
        cv[p] = make_int2(__ldg(ecol + i), __float_as_int(__ldg(eval + i)));
    }
}

// ---------------------------------------------------------------------------
// GEMM1 (tensor core): H[n,64] fp16 = X[n,128] fp32 @ W1[128,64]
// Tile: 128 rows/block, 256 thr (8 warps), warp = 16 rows x 64 cols.
// smem: xs[128][136] fp16 (X converted), ws[64][136] fp16 (W1^T n-major).
// Stride 136 halfs = 68 words = 4 mod 32 -> fragment LDS conflict-free.
// ---------------------------------------------------------------------------
#define XS1 136
__global__ __launch_bounds__(256) void gemm_in_tc(
    const float* __restrict__ X, const __half* __restrict__ Wt,
    __half* __restrict__ H, int n)
{
    extern __shared__ __half sm1[];
    __half* xs = sm1;               // [128][136]
    __half* ws = sm1 + 128 * XS1;   // [64][136]

    const int tid  = threadIdx.x;
    const int row0 = blockIdx.x * 128;

    // ws <- Wt [64][128] (uint4 = 8 halfs)
    for (int idx = tid; idx < 64 * 16; idx += 256) {
        int r = idx >> 4, c = idx & 15;
        uint4 v = *reinterpret_cast<const uint4*>(Wt + r * 128 + c * 8);
        *reinterpret_cast<uint4*>(ws + r * XS1 + c * 8) = v;
    }
    // xs <- fp16(X tile)
    for (int idx = tid; idx < 128 * 16; idx += 256) {
        int r = idx >> 4, c = idx & 15;
        int gr = row0 + r;
        uint4 o = make_uint4(0u, 0u, 0u, 0u);
        if (gr < n) {
            const float4* p = reinterpret_cast<const float4*>(X + (size_t)gr * INF + c * 8);
            float4 f0 = __ldg(p);
            float4 f1 = __ldg(p + 1);
            o.x = pack_h2(f0.x, f0.y); o.y = pack_h2(f0.z, f0.w);
            o.z = pack_h2(f1.x, f1.y); o.w = pack_h2(f1.z, f1.w);
        }
        *reinterpret_cast<uint4*>(xs + r * XS1 + c * 8) = o;
    }
    __syncthreads();

    const int warp = tid >> 5, lane = tid & 31;
    const int g = lane >> 2, tg = lane & 3;
    const int m0 = warp * 16;

    float acc[8][4];
    #pragma unroll
    for (int i = 0; i < 8; i++)
        #pragma unroll
        for (int j = 0; j < 4; j++) acc[i][j] = 0.f;

    const __half* xb = xs + (m0 + g) * XS1 + 2 * tg;
    const __half* wb = ws + g * XS1 + 2 * tg;

    #pragma unroll
    for (int kb = 0; kb < 128; kb += 16) {
        uint32_t a0 = *reinterpret_cast<const uint32_t*>(xb + kb);
        uint32_t a1 = *reinterpret_cast<const uint32_t*>(xb + kb + 8 * XS1);
        uint32_t a2 = *reinterpret_cast<const uint32_t*>(xb + kb + 8);
        uint32_t a3 = *reinterpret_cast<const uint32_t*>(xb + kb + 8 * XS1 + 8);
        #pragma unroll
        for (int nf = 0; nf < 8; nf++) {
            uint32_t b0 = *reinterpret_cast<const uint32_t*>(wb + nf * 8 * XS1 + kb);
            uint32_t b1 = *reinterpret_cast<const uint32_t*>(wb + nf * 8 * XS1 + kb + 8);
            mma16816(acc[nf], a0, a1, a2, a3, b0, b1);
        }
    }

    const int r1 = row0 + m0 + g, r2 = r1 + 8;
    #pragma unroll
    for (int nf = 0; nf < 8; nf++) {
        int col = nf * 8 + 2 * tg;
        if (r1 < n)
            *reinterpret_cast<uint32_t*>(H + (size_t)r1 * HID + col) = pack_h2(acc[nf][0], acc[nf][1]);
        if (r2 < n)
            *reinterpret_cast<uint32_t*>(H + (size_t)r2 * HID + col) = pack_h2(acc[nf][2], acc[nf][3]);
    }
}

// ---------------------------------------------------------------------------
// GEMM2 (tensor core): H2[n,64] fp16 = H1[n,64] fp16 @ W2[64,64]
// Same layout, K=64, stride 72 halfs (36 words = 4 mod 32).
// ---------------------------------------------------------------------------
#define XS2 72
__global__ __launch_bounds__(256) void gemm_hid_tc(
    const __half* __restrict__ Hin, const __half* __restrict__ Wt,
    __half* __restrict__ Hout, int n)
{
    __shared__ __half xs[128 * XS2];
    __shared__ __half ws[64 * XS2];

    const int tid  = threadIdx.x;
    const int row0 = blockIdx.x * 128;

    for (int idx = tid; idx < 64 * 8; idx += 256) {
        int r = idx >> 3, c = idx & 7;
        uint4 v = *reinterpret_cast<const uint4*>(Wt + r * 64 + c * 8);
        *reinterpret_cast<uint4*>(ws + r * XS2 + c * 8) = v;
    }
    for (int idx = tid; idx < 128 * 8; idx += 256) {
        int r = idx >> 3, c = idx & 7;
        int gr = row0 + r;
        uint4 v = make_uint4(0u, 0u, 0u, 0u);
        if (gr < n)
            v = __ldg(reinterpret_cast<const uint4*>(Hin + (size_t)gr * HID + c * 8));
        *reinterpret_cast<uint4*>(xs + r * XS2 + c * 8) = v;
    }
    __syncthreads();

    const int warp = tid >> 5, lane = tid & 31;
    const int g = lane >> 2, tg = lane & 3;
    const int m0 = warp * 16;

    float acc[8][4];
    #pragma unroll
    for (int i = 0; i < 8; i++)
        #pragma unroll
        for (int j = 0; j < 4; j++) acc[i][j] = 0.f;

    const __half* xb = xs + (m0 + g) * XS2 + 2 * tg;
    const __half* wb = ws + g * XS2 + 2 * tg;

    #pragma unroll
    for (int kb = 0; kb < 64; kb += 16) {
        uint32_t a0 = *reinterpret_cast<const uint32_t*>(xb + kb);
        uint32_t a1 = *reinterpret_cast<const uint32_t*>(xb + kb + 8 * XS2);
        uint32_t a2 = *reinterpret_cast<const uint32_t*>(xb + kb + 8);
        uint32_t a3 = *reinterpret_cast<const uint32_t*>(xb + kb + 8 * XS2 + 8);
        #pragma unroll
        for (int nf = 0; nf < 8; nf++) {
            uint32_t b0 = *reinterpret_cast<const uint32_t*>(wb + nf * 8 * XS2 + kb);
            uint32_t b1 = *reinterpret_cast<const uint32_t*>(wb + nf * 8 * XS2 + kb + 8);
            mma16816(acc[nf], a0, a1, a2, a3, b0, b1);
        }
    }

    const int r1 = row0 + m0 + g, r2 = r1 + 8;
    #pragma unroll
    for (int nf = 0; nf < 8; nf++) {
        int col = nf * 8 + 2 * tg;
        if (r1 < n)
            *reinterpret_cast<uint32_t*>(Hout + (size_t)r1 * HID + col) = pack_h2(acc[nf][0], acc[nf][1]);
        if (r2 < n)
            *reinterpret_cast<uint32_t*>(Hout + (size_t)r2 * HID + col) = pack_h2(acc[nf][2], acc[nf][3]);
    }
}

// ---------------------------------------------------------------------------
// SpMM core: warp per dest row; 4 edges per gather instruction.
// ---------------------------------------------------------------------------
#define SPMM_BODY                                                              \
    int g = lane >> 3;                                                         \
    int q = lane & 7;                                                          \
    int s = __ldg(rptr + row);                                                 \
    int e = __ldg(rptr + row + 1);                                             \
    float2 a0 = make_float2(0.f, 0.f), a1 = make_float2(0.f, 0.f);             \
    float2 a2 = make_float2(0.f, 0.f), a3 = make_float2(0.f, 0.f);             \
    _Pragma("unroll 2")                                                        \
    for (int i = s; i < e; i += 8) {                                           \
        int  iA = i + g,      iB = i + 4 + g;                                  \
        bool vA = iA < e,     vB = iB < e;                                     \
        int2 cA = __ldg(cv + (vA ? iA : s));                                   \
        int2 cB = __ldg(cv + (vB ? iB : s));                                   \
        float wA = vA ? __int_as_float(cA.y) : 0.f;                            \
        float wB = vB ? __int_as_float(cB.y) : 0.f;                            \
        uint4 rA = __ldg(reinterpret_cast<const uint4*>(src + (size_t)cA.x * HID) + q); \
        uint4 rB = __ldg(reinterpret_cast<const uint4*>(src + (size_t)cB.x * HID) + q); \
        float2 f;                                                              \
        f = __half22float2(*reinterpret_cast<__half2*>(&rA.x));                \
        a0.x = fmaf(wA, f.x, a0.x); a0.y = fmaf(wA, f.y, a0.y);                \
        f = __half22float2(*reinterpret_cast<__half2*>(&rA.y));                \
        a1.x = fmaf(wA, f.x, a1.x); a1.y = fmaf(wA, f.y, a1.y);                \
        f = __half22float2(*reinterpret_cast<__half2*>(&rA.z));                \
        a2.x = fmaf(wA, f.x, a2.x); a2.y = fmaf(wA, f.y, a2.y);                \
        f = __half22float2(*reinterpret_cast<__half2*>(&rA.w));                \
        a3.x = fmaf(wA, f.x, a3.x); a3.y = fmaf(wA, f.y, a3.y);                \
        f = __half22float2(*reinterpret_cast<__half2*>(&rB.x));                \
        a0.x = fmaf(wB, f.x, a0.x); a0.y = fmaf(wB, f.y, a0.y);                \
        f = __half22float2(*reinterpret_cast<__half2*>(&rB.y));                \
        a1.x = fmaf(wB, f.x, a1.x); a1.y = fmaf(wB, f.y, a1.y);                \
        f = __half22float2(*reinterpret_cast<__half2*>(&rB.z));                \
        a2.x = fmaf(wB, f.x, a2.x); a2.y = fmaf(wB, f.y, a2.y);                \
        f = __half22float2(*reinterpret_cast<__half2*>(&rB.w));                \
        a3.x = fmaf(wB, f.x, a3.x); a3.y = fmaf(wB, f.y, a3.y);                \
    }                                                                          \
    _Pragma("unroll")                                                          \
    for (int off = 8; off <= 16; off <<= 1) {                                  \
        a0.x += __shfl_xor_sync(0xFFFFFFFFu, a0.x, off);                       \
        a0.y += __shfl_xor_sync(0xFFFFFFFFu, a0.y, off);                       \
        a1.x += __shfl_xor_sync(0xFFFFFFFFu, a1.x, off);                       \
        a1.y += __shfl_xor_sync(0xFFFFFFFFu, a1.y, off);                       \
        a2.x += __shfl_xor_sync(0xFFFFFFFFu, a2.x, off);                       \
        a2.y += __shfl_xor_sync(0xFFFFFFFFu, a2.y, off);                       \
        a3.x += __shfl_xor_sync(0xFFFFFFFFu, a3.x, off);                       \
        a3.y += __shfl_xor_sync(0xFFFFFFFFu, a3.y, off);                       \
    }

// Layer-1 SpMM: epilogue relu(acc + b1), store fp16 row (lanes 0-7 store uint4)
__global__ __launch_bounds__(256) void spmm_relu_kernel(
    const int* __restrict__ rptr, const int2* __restrict__ cv,
    const __half* __restrict__ src, const float* __restrict__ b1,
    __half* __restrict__ dst, int n)
{
    int row  = (blockIdx.x * blockDim.x + threadIdx.x) >> 5;
    int lane = threadIdx.x & 31;
    if (row >= n) return;

    SPMM_BODY

    if (g == 0) {
        float4 bA = __ldg(reinterpret_cast<const float4*>(b1) + 2 * q);
        float4 bB = __ldg(reinterpret_cast<const float4*>(b1) + 2 * q + 1);
        float r0 = fmaxf(a0.x + bA.x, 0.f), r1 = fmaxf(a0.y + bA.y, 0.f);
        float r2 = fmaxf(a1.x + bA.z, 0.f), r3 = fmaxf(a1.y + bA.w, 0.f);
        float r4 = fmaxf(a2.x + bB.x, 0.f), r5 = fmaxf(a2.y + bB.y, 0.f);
        float r6 = fmaxf(a3.x + bB.z, 0.f), r7 = fmaxf(a3.y + bB.w, 0.f);
        uint4 pv = make_uint4(pack_h2(r0, r1), pack_h2(r2, r3),
                              pack_h2(r4, r5), pack_h2(r6, r7));
        reinterpret_cast<uint4*>(dst + (size_t)row * HID)[q] = pv;
    }
}

// Layer-2 SpMM fused head: relu(acc + b2) . linW, + linb -> out[row]
__global__ __launch_bounds__(256) void spmm_head_kernel(
    const int* __restrict__ rptr, const int2* __restrict__ cv,
    const __half* __restrict__ src,
    const float* __restrict__ b2, const float* __restrict__ linW,
    const float* __restrict__ linb, float* __restrict__ out, int n)
{
    int row  = (blockIdx.x * blockDim.x + threadIdx.x) >> 5;
    int lane = threadIdx.x & 31;
    if (row >= n) return;

    SPMM_BODY

    float4 bA = __ldg(reinterpret_cast<const float4*>(b2) + 2 * q);
    float4 bB = __ldg(reinterpret_cast<const float4*>(b2) + 2 * q + 1);
    float4 wA = __ldg(reinterpret_cast<const float4*>(linW) + 2 * q);
    float4 wB = __ldg(reinterpret_cast<const float4*>(linW) + 2 * q + 1);
    float sum = fmaxf(a0.x + bA.x, 0.f) * wA.x + fmaxf(a0.y + bA.y, 0.f) * wA.y
              + fmaxf(a1.x + bA.z, 0.f) * wA.z + fmaxf(a1.y + bA.w, 0.f) * wA.w
              + fmaxf(a2.x + bB.x, 0.f) * wB.x + fmaxf(a2.y + bB.y, 0.f) * wB.y
              + fmaxf(a3.x + bB.z, 0.f) * wB.z + fmaxf(a3.y + bB.w, 0.f) * wB.w;
    #pragma unroll
    for (int off = 1; off <= 4; off <<= 1)
        sum += __shfl_xor_sync(0xFFFFFFFFu, sum, off);
    if (lane == 0) out[row] = sum + __ldg(linb);
}

// ---------------------------------------------------------------------------
// kernel_launch
// Inputs: x, edge_row, edge_col, edge_val, W1, b1, W2, b2, lin_W, lin_b
// ---------------------------------------------------------------------------
extern "C" void kernel_launch(void* const* d_in, const int* in_sizes, int n_in,
                              void* d_out, int out_size)
{
    const float* x    = (const float*)d_in[0];
    const int*   erow = (const int*)  d_in[1];
    const int*   ecol = (const int*)  d_in[2];
    const float* eval = (const float*)d_in[3];
    const float* W1   = (const float*)d_in[4];
    const float* b1   = (const float*)d_in[5];
    const float* W2   = (const float*)d_in[6];
    const float* b2   = (const float*)d_in[7];
    const float* linW = (const float*)d_in[8];
    const float* linb = (const float*)d_in[9];
    float* out = (float*)d_out;

    const int n = in_sizes[0] / INF;
    const int E = in_sizes[1];

    __half *hA, *hB, *w1t, *w2t;
    int *deg, *rptr, *wcur, *partial;
    int2 *cv;
    cudaGetSymbolAddress((void**)&hA,   g_hA);
    cudaGetSymbolAddress((void**)&hB,   g_hB);
    cudaGetSymbolAddress((void**)&w1t,  g_w1t);
    cudaGetSymbolAddress((void**)&w2t,  g_w2t);
    cudaGetSymbolAddress((void**)&deg,  g_deg);
    cudaGetSymbolAddress((void**)&rptr, g_rptr);
    cudaGetSymbolAddress((void**)&wcur, g_wcur);
    cudaGetSymbolAddress((void**)&cv,   g_cv);
    cudaGetSymbolAddress((void**)&partial, g_partial);

    static bool init_done = false;
    static cudaStream_t side = nullptr;
    static cudaEvent_t evFork = nullptr, evJoin = nullptr;
    if (!init_done) {
        cudaFuncSetAttribute(gemm_in_tc,
                             cudaFuncAttributeMaxDynamicSharedMemorySize, 65536);
        cudaStreamCreateWithFlags(&side, cudaStreamNonBlocking);
        cudaEventCreateWithFlags(&evFork, cudaEventDisableTiming);
        cudaEventCreateWithFlags(&evJoin, cudaEventDisableTiming);
        init_done = true;
    }

    const int nb         = (n + 1023) / 1024;     // scan blocks (<=128)
    const int tc_grid    = (n + 127) / 128;       // 128-row tiles
    const int spmm_grid  = (n * 32 + 255) / 256;  // warp per row
    const int egrid      = 2048;
    const int smem1      = (128 * XS1 + 64 * XS1) * (int)sizeof(__half);

    // --- Fork: CSR build on side stream, overlapped with main-stream GEMM1 ---
    cudaEventRecord(evFork, 0);
    cudaStreamWaitEvent(side, evFork, 0);
    zero_deg_kernel<<<256, 256, 0, side>>>(deg, n);
    hist_kernel<<<egrid, 256, 0, side>>>(erow, deg, E);
    partial_kernel<<<nb, 256, 0, side>>>(deg, partial, n);
    scanp_kernel<<<1, 128, 0, side>>>(partial, rptr, nb, n);
    scan_chunk_kernel<<<nb, 256, 0, side>>>(deg, partial, rptr, wcur, n);
    scatter_kernel<<<egrid, 256, 0, side>>>(erow, ecol, eval, wcur, cv, E);
    cudaEventRecord(evJoin, side);

    // --- Main stream: weight convert + GEMM1 (tensor cores) ---
    wconv_kernel<<<48, 256>>>(W1, W2, w1t, w2t);
    gemm_in_tc<<<tc_grid, 256, smem1>>>(x, w1t, hA, n);

    // --- Join, then layer-1 SpMM (+bias1+relu): hB = relu(A@hA + b1) ---
    cudaStreamWaitEvent(0, evJoin, 0);
    spmm_relu_kernel<<<spmm_grid, 256>>>(rptr, cv, hA, b1, hB, n);

    // --- Layer 2: hA = hB @ W2 ; out = head(A@hA) ---
    gemm_hid_tc<<<tc_grid, 256>>>(hB, w2t, hA, n);
    spmm_head_kernel<<<spmm_grid, 256>>>(rptr, cv, hA, b2, linW, linb, out, n);
}